// round 14
// baseline (speedup 1.0000x reference)
#include <cuda_runtime.h>
#include <cuda_bf16.h>
#include <math.h>
#include <stdint.h>

// Problem constants
#define BATCH   2
#define LSEQ    2048
#define DMODEL  1024
#define DINNER  2048
#define NSTATE  16
#define KCONV   4
#define MTOT    (BATCH * LSEQ)      // 4096

// ---------------------------------------------------------------------------
// Static scratch
// ---------------------------------------------------------------------------
__device__ float g_xz[MTOT * DINNER];
__device__ float g_xg[MTOT * DINNER];
__device__ float g_act[MTOT * DINNER];
__device__ float g_delta[MTOT * DINNER];
__device__ float g_Bm[MTOT * NSTATE];
__device__ float g_Cm[MTOT * NSTATE];

// tf32-rounded fp32 GEMM operands
__device__ float g_xt[MTOT * DMODEL];      // rounded x
__device__ float g_at[MTOT * DINNER];      // rounded act
__device__ float g_gt[MTOT * DINNER];      // rounded gated
__device__ float g_wt[DINNER * DINNER];    // rounded transposed weights (reused)

// ---------------------------------------------------------------------------
// PTX helpers
// ---------------------------------------------------------------------------
__device__ __forceinline__ uint32_t smem_u32(const void* p) {
    uint32_t a;
    asm("{ .reg .u64 t; cvta.to.shared.u64 t, %1; cvt.u32.u64 %0, t; }"
        : "=r"(a) : "l"(p));
    return a;
}
__device__ __forceinline__ void cpa16(uint32_t dst, const void* src) {
    asm volatile("cp.async.cg.shared.global [%0], [%1], 16;"
                 :: "r"(dst), "l"(src));
}
__device__ __forceinline__ uint32_t lds32(uint32_t addr) {
    uint32_t v;
    asm volatile("ld.shared.b32 %0, [%1];" : "=r"(v) : "r"(addr));
    return v;
}
__device__ __forceinline__ float to_tf32(float f) {
    uint32_t o, i = __float_as_uint(f);
    asm("cvt.rna.tf32.f32 %0, %1;" : "=r"(o) : "r"(i));
    return __uint_as_float(o);
}
__device__ __forceinline__ void mma_tf32(float* d, const uint32_t* a,
                                         uint32_t b0, uint32_t b1) {
    asm volatile(
        "mma.sync.aligned.m16n8k8.row.col.f32.tf32.tf32.f32 "
        "{%0,%1,%2,%3}, {%4,%5,%6,%7}, {%8,%9}, {%0,%1,%2,%3};"
        : "+f"(d[0]), "+f"(d[1]), "+f"(d[2]), "+f"(d[3])
        : "r"(a[0]), "r"(a[1]), "r"(a[2]), "r"(a[3]), "r"(b0), "r"(b1));
}

// ---------------------------------------------------------------------------
// tf32 mma.sync GEMM (identical to R13 — proven 233us on the fused shape)
// ---------------------------------------------------------------------------
#define MG_STAGE  16384        // A(8K) + B(8K)

__device__ __forceinline__ void load_stage(uint32_t sstage,
        const float* __restrict__ A, const float* __restrict__ B,
        int arow0, int brow0, int K, int kc, int tid)
{
#pragma unroll
    for (int it = 0; it < 2; it++) {
        const int idx = tid + 256 * it;      // 0..511
        const int rr  = idx >> 2;            // row 0..127
        const int c4  = idx & 3;             // 16B chunk
        const uint32_t soff = rr * 64 + ((c4 ^ ((rr >> 1) & 3)) << 4);
        cpa16(sstage +        soff, A + (size_t)(arow0 + rr) * K + kc + c4 * 4);
        cpa16(sstage + 8192 + soff, B + (size_t)(brow0 + rr) * K + kc + c4 * 4);
    }
}

template<int EPI>   // 0: bias, 1: bias + softplus
__global__ __launch_bounds__(256, 2)
void mmagemm(const float* __restrict__ A, const float* __restrict__ B,
             const float* __restrict__ bias0, const float* __restrict__ bias1,
             float* __restrict__ C0, float* __restrict__ C1,
             int Nout, int Nsplit, int K)
{
    __shared__ char smem[3 * MG_STAGE];     // 48 KB static
    const uint32_t sb = smem_u32(smem);
    const int tid  = threadIdx.x;
    const int wid  = tid >> 5;
    const int lane = tid & 31;
    const int warp_m = wid & 1;
    const int warp_n = wid >> 1;
    const int arow0 = blockIdx.y * 128;
    const int brow0 = blockIdx.x * 128;

    const int rA = lane >> 2;                 // 0..7
    const int cA = lane & 3;                  // 0..3
    const int swz = ((rA >> 1) & 3) << 2;
    uint32_t kx[2], kx4[2];
#pragma unroll
    for (int s = 0; s < 2; s++) {
        kx[s]  = (uint32_t)(((s * 8 + cA)     ^ swz) << 2);
        kx4[s] = (uint32_t)(((s * 8 + cA + 4) ^ swz) << 2);
    }
    const int m0 = warp_m * 64;
    const int n0 = warp_n * 32;

    float acc[4][4][4];
#pragma unroll
    for (int a = 0; a < 4; a++)
#pragma unroll
        for (int b = 0; b < 4; b++)
#pragma unroll
            for (int c = 0; c < 4; c++) acc[a][b][c] = 0.f;

    const int nch = K >> 4;

    load_stage(sb,            A, B, arow0, brow0, K, 0,  tid);
    asm volatile("cp.async.commit_group;");
    load_stage(sb + MG_STAGE, A, B, arow0, brow0, K, 16, tid);
    asm volatile("cp.async.commit_group;");

    int stage = 0;
    for (int i = 0; i < nch; i++) {
        if (i + 1 < nch) {
            asm volatile("cp.async.wait_group 1;");
        } else {
            asm volatile("cp.async.wait_group 0;");
        }
        __syncthreads();

        if (i + 2 < nch) {
            int ns = stage + 2; if (ns >= 3) ns -= 3;
            load_stage(sb + ns * MG_STAGE, A, B, arow0, brow0, K, (i + 2) * 16, tid);
            asm volatile("cp.async.commit_group;");
        }

        const uint32_t st = sb + stage * MG_STAGE;
#pragma unroll
        for (int ks = 0; ks < 2; ks++) {
            uint32_t bf[4][2];
#pragma unroll
            for (int nt = 0; nt < 4; nt++) {
                const uint32_t rb = st + 8192 + (n0 + nt * 8 + rA) * 64;
                bf[nt][0] = lds32(rb + kx[ks]);
                bf[nt][1] = lds32(rb + kx4[ks]);
            }
#pragma unroll
            for (int mt = 0; mt < 4; mt++) {
                const uint32_t ra = st + (m0 + mt * 16 + rA) * 64;
                uint32_t af[4];
                af[0] = lds32(ra +       kx[ks]);
                af[1] = lds32(ra + 512 + kx[ks]);
                af[2] = lds32(ra +       kx4[ks]);
                af[3] = lds32(ra + 512 + kx4[ks]);
#pragma unroll
                for (int nt = 0; nt < 4; nt++)
                    mma_tf32(acc[mt][nt], af, bf[nt][0], bf[nt][1]);
            }
        }
        if (++stage == 3) stage = 0;
    }

    const float* bias = bias0;
    float* Cp = C0;
    int colbase = brow0;
    if (brow0 >= Nsplit) { bias = bias1; Cp = C1; colbase = brow0 - Nsplit; }

    const int gid = lane >> 2, tig = lane & 3;
#pragma unroll
    for (int mt = 0; mt < 4; mt++) {
        const int r0 = arow0 + m0 + mt * 16 + gid;
#pragma unroll
        for (int nt = 0; nt < 4; nt++) {
            const int col = colbase + n0 + nt * 8 + tig * 2;
            const float bb0 = __ldg(bias + col);
            const float bb1 = __ldg(bias + col + 1);
            float v0 = acc[mt][nt][0] + bb0;
            float v1 = acc[mt][nt][1] + bb1;
            float v2 = acc[mt][nt][2] + bb0;
            float v3 = acc[mt][nt][3] + bb1;
            if (EPI == 1) {
                v0 = (v0 > 20.f) ? v0 : log1pf(expf(v0));
                v1 = (v1 > 20.f) ? v1 : log1pf(expf(v1));
                v2 = (v2 > 20.f) ? v2 : log1pf(expf(v2));
                v3 = (v3 > 20.f) ? v3 : log1pf(expf(v3));
            }
            float2 p01; p01.x = v0; p01.y = v1;
            float2 p23; p23.x = v2; p23.y = v3;
            *(float2*)(Cp + (size_t)r0 * Nout + col)       = p01;
            *(float2*)(Cp + (size_t)(r0 + 8) * Nout + col) = p23;
        }
    }
}

// ---------------------------------------------------------------------------
// Elementwise tf32 rounding (for input x)
// ---------------------------------------------------------------------------
__global__ __launch_bounds__(256)
void round_tf32(const float* __restrict__ in, float* __restrict__ out, int n4)
{
    const int i = blockIdx.x * 256 + threadIdx.x;
    if (i >= n4) return;
    float4 v = ((const float4*)in)[i];
    v.x = to_tf32(v.x); v.y = to_tf32(v.y);
    v.z = to_tf32(v.z); v.w = to_tf32(v.w);
    ((float4*)out)[i] = v;
}

// ---------------------------------------------------------------------------
// Weight transpose + tf32 round: W[K,N] -> T[N,K]
// ---------------------------------------------------------------------------
__global__ void transpose_tf32(const float* __restrict__ W, int K, int N,
                               float* __restrict__ T)
{
    __shared__ float ts[32][33];
    const int n0 = blockIdx.x * 32, k0 = blockIdx.y * 32;
    const int tx = threadIdx.x, ty = threadIdx.y;
#pragma unroll
    for (int i = 0; i < 4; i++)
        ts[ty + i * 8][tx] = W[(size_t)(k0 + ty + i * 8) * N + n0 + tx];
    __syncthreads();
#pragma unroll
    for (int i = 0; i < 4; i++)
        T[(size_t)(n0 + ty + i * 8) * K + k0 + tx] = to_tf32(ts[tx][ty + i * 8]);
}

// ---------------------------------------------------------------------------
// Causal depthwise conv (K=4) + bias + silu; outputs exact act + rounded copy
// ---------------------------------------------------------------------------
__global__ __launch_bounds__(256)
void conv_silu(const float* __restrict__ xz, const float* __restrict__ w,
               const float* __restrict__ cb, float* __restrict__ act,
               float* __restrict__ act_t)
{
    const int idx = blockIdx.x * 256 + threadIdx.x;
    if (idx >= MTOT * DINNER) return;
    const int d = idx & (DINNER - 1);
    const int bt = idx >> 11;
    const int t = bt & (LSEQ - 1);

    float s = __ldg(cb + d);
#pragma unroll
    for (int k = 0; k < KCONV; k++) {
        const int tt = t - (KCONV - 1) + k;
        if (tt >= 0)
            s = fmaf(__ldg(w + d * KCONV + k), xz[idx + (k - (KCONV - 1)) * DINNER], s);
    }
    const float v = s / (1.f + __expf(-s));
    act[idx]   = v;
    act_t[idx] = to_tf32(v);
}

// ---------------------------------------------------------------------------
// Skinny GEMM: Bm = act @ W_B, Cm = act @ W_C   (fp32, precision-critical)
// ---------------------------------------------------------------------------
__global__ __launch_bounds__(256)
void bc_gemm(const float* __restrict__ act,
             const float* __restrict__ WB, const float* __restrict__ WC,
             float* __restrict__ Bm, float* __restrict__ Cm)
{
    const int m = blockIdx.x * 16 + (threadIdx.x >> 4);
    const int n = threadIdx.x & 15;
    const float* a = act + (size_t)m * DINNER;

    float sb = 0.f, sc = 0.f;
#pragma unroll 8
    for (int k = 0; k < DINNER; k++) {
        const float av = a[k];
        sb = fmaf(av, __ldg(WB + k * NSTATE + n), sb);
        sc = fmaf(av, __ldg(WC + k * NSTATE + n), sc);
    }
    Bm[m * NSTATE + n] = sb;
    Cm[m * NSTATE + n] = sc;
}

// ---------------------------------------------------------------------------
// Selective scan + skip + gating.
// Block = 16 consecutive d channels of one batch; smem-staged coalesced I/O;
// recurrence first, then 8 independent pipelined butterfly reductions.
// Arithmetic identical to previous version (bitwise-same output).
// ---------------------------------------------------------------------------
__global__ __launch_bounds__(256)
void scan_kernel(const float* __restrict__ delta, const float* __restrict__ act,
                 const float* __restrict__ Bm, const float* __restrict__ Cm,
                 const float* __restrict__ A_log, const float* __restrict__ D_skip,
                 const float* __restrict__ xg, float* __restrict__ gt)
{
    __shared__ float sD[8][16], sX[8][16], sG[8][16];
    __shared__ float sB[8][16], sC[8][16], sO[8][16];

    const int tid  = threadIdx.x;
    const int ws   = tid >> 5;
    const int lane = tid & 31;
    const int bid  = blockIdx.x;            // 256 blocks
    const int b    = bid >> 7;              // 128 blocks per batch
    const int d0   = (bid & 127) * 16;
    const int n    = lane & 15;
    const int dloc = ws * 2 + (lane >> 4);  // 0..15
    const int d    = d0 + dloc;

    const float a   = -expf(A_log[d * NSTATE + n]);
    const float dsk = D_skip[d];
    const size_t rowbase = (size_t)b * LSEQ;

    float h = 0.f;
    for (int t0 = 0; t0 < LSEQ; t0 += 8) {
        // Cooperative coalesced staging: 5 tiles x 128 elements
        for (int e = tid; e < 640; e += 256) {
            const int j  = (e >> 4) & 7;
            const int dd = e & 15;
            const int which = e >> 7;
            const size_t rb = rowbase + t0 + j;
            if (which == 0)      sD[j][dd] = delta[rb * DINNER + d0 + dd];
            else if (which == 1) sX[j][dd] = act  [rb * DINNER + d0 + dd];
            else if (which == 2) sG[j][dd] = xg   [rb * DINNER + d0 + dd];
            else if (which == 3) sB[j][dd] = Bm   [rb * NSTATE + dd];
            else                 sC[j][dd] = Cm   [rb * NSTATE + dd];
        }
        __syncthreads();

        float dv[8], xv[8], bv[8], cv[8], dA[8], p[8];
#pragma unroll
        for (int j = 0; j < 8; j++) {
            dv[j] = sD[j][dloc];
            xv[j] = sX[j][dloc];
            bv[j] = sB[j][n];
            cv[j] = sC[j][n];
        }
#pragma unroll
        for (int j = 0; j < 8; j++) dA[j] = __expf(dv[j] * a);
#pragma unroll
        for (int j = 0; j < 8; j++) {
            h = fmaf(dA[j], h, (dv[j] * xv[j]) * bv[j]);
            p[j] = h * cv[j];
        }
        // 8 independent butterfly chains — pipelined, same add order as before
#pragma unroll
        for (int s = 1; s <= 8; s <<= 1) {
#pragma unroll
            for (int j = 0; j < 8; j++)
                p[j] += __shfl_xor_sync(0xffffffffu, p[j], s);
        }
        if (n == 0) {
#pragma unroll
            for (int j = 0; j < 8; j++) {
                const float g = sG[j][dloc];
                const float y = (p[j] + xv[j] * dsk) * (g / (1.f + __expf(-g)));
                sO[j][dloc] = to_tf32(y);
            }
        }
        __syncthreads();

        // Coalesced write-out of the 8x16 output tile
        for (int e = tid; e < 128; e += 256) {
            const int j  = e >> 4;
            const int dd = e & 15;
            gt[(rowbase + t0 + j) * DINNER + d0 + dd] = sO[j][dd];
        }
        __syncthreads();
    }
}

// ---------------------------------------------------------------------------
// Launch
// ---------------------------------------------------------------------------
extern "C" void kernel_launch(void* const* d_in, const int* in_sizes, int n_in,
                              void* d_out, int out_size)
{
    const float* x      = (const float*)d_in[0];
    const float* W_in   = (const float*)d_in[1];
    const float* b_in   = (const float*)d_in[2];
    const float* W_gate = (const float*)d_in[3];
    const float* b_gate = (const float*)d_in[4];
    const float* conv_w = (const float*)d_in[5];
    const float* conv_b = (const float*)d_in[6];
    const float* A_log  = (const float*)d_in[7];
    const float* D_skip = (const float*)d_in[8];
    const float* W_delta= (const float*)d_in[9];
    const float* b_delta= (const float*)d_in[10];
    const float* W_B    = (const float*)d_in[11];
    const float* W_C    = (const float*)d_in[12];
    const float* W_out  = (const float*)d_in[13];
    const float* b_out  = (const float*)d_in[14];
    float* out = (float*)d_out;

    float *xz, *xg, *act, *delt, *Bm, *Cm, *xt, *at, *gt, *wt;
    cudaGetSymbolAddress((void**)&xz,   g_xz);
    cudaGetSymbolAddress((void**)&xg,   g_xg);
    cudaGetSymbolAddress((void**)&act,  g_act);
    cudaGetSymbolAddress((void**)&delt, g_delta);
    cudaGetSymbolAddress((void**)&Bm,   g_Bm);
    cudaGetSymbolAddress((void**)&Cm,   g_Cm);
    cudaGetSymbolAddress((void**)&xt,   g_xt);
    cudaGetSymbolAddress((void**)&at,   g_at);
    cudaGetSymbolAddress((void**)&gt,   g_gt);
    cudaGetSymbolAddress((void**)&wt,   g_wt);

    // 0) round x -> tf32
    {
        const int n4 = MTOT * DMODEL / 4;
        round_tf32<<<(n4 + 255) / 256, 256>>>(x, xt, n4);
    }
    // 1) fused in+gate: [xz | xg] = x @ [W_in | W_gate] + [b_in | b_gate]
    {
        dim3 tg(DINNER / 32, DMODEL / 32);
        transpose_tf32<<<tg, dim3(32, 8)>>>(W_in,   DMODEL, DINNER, wt);
        transpose_tf32<<<tg, dim3(32, 8)>>>(W_gate, DMODEL, DINNER,
                                            wt + (size_t)DINNER * DMODEL);
        dim3 grid(2 * DINNER / 128, MTOT / 128);     // 32 x 32
        mmagemm<0><<<grid, 256>>>(xt, wt, b_in, b_gate,
                                  xz, xg, DINNER, DINNER, DMODEL);
    }
    // 2) act = silu(conv(xz) + conv_b)  (+ tf32 copy)
    {
        const int total = MTOT * DINNER;
        conv_silu<<<(total + 255) / 256, 256>>>(xz, conv_w, conv_b, act, at);
    }
    // 3) delta = softplus(act @ W_delta + b_delta)
    {
        dim3 tg(DINNER / 32, DINNER / 32);
        transpose_tf32<<<tg, dim3(32, 8)>>>(W_delta, DINNER, DINNER, wt);
        dim3 grid(DINNER / 128, MTOT / 128);
        mmagemm<1><<<grid, 256>>>(at, wt, b_delta, b_delta,
                                  delt, delt, DINNER, DINNER, DINNER);
    }
    // 4) Bm, Cm
    {
        bc_gemm<<<MTOT / 16, 256>>>(act, W_B, W_C, Bm, Cm);
    }
    // 5) scan + skip + gating -> gt (tf32-rounded)
    {
        scan_kernel<<<(BATCH * DINNER) / 16, 256>>>(delt, act, Bm, Cm,
                                                    A_log, D_skip, xg, gt);
    }
    // 6) out = gated @ W_out + b_out
    {
        dim3 tg(DMODEL / 32, DINNER / 32);
        transpose_tf32<<<tg, dim3(32, 8)>>>(W_out, DINNER, DMODEL, wt);
        dim3 grid(DMODEL / 128, MTOT / 128);
        mmagemm<0><<<grid, 256>>>(gt, wt, b_out, b_out,
                                  out, out, DMODEL, DMODEL, DINNER);
    }
}

// round 15
// speedup vs baseline: 1.1766x; 1.1766x over previous
#include <cuda_runtime.h>
#include <cuda_bf16.h>
#include <math.h>
#include <stdint.h>

// Problem constants
#define BATCH   2
#define LSEQ    2048
#define DMODEL  1024
#define DINNER  2048
#define NSTATE  16
#define KCONV   4
#define MTOT    (BATCH * LSEQ)      // 4096

// ---------------------------------------------------------------------------
// Static scratch
// ---------------------------------------------------------------------------
__device__ float g_xz[MTOT * DINNER];
__device__ float g_xg[MTOT * DINNER];
__device__ float g_act[MTOT * DINNER];
__device__ float g_delta[MTOT * DINNER];
__device__ float g_Bm[MTOT * NSTATE];
__device__ float g_Cm[MTOT * NSTATE];

// tf32-rounded fp32 GEMM operands
__device__ float g_xt[MTOT * DMODEL];      // rounded x
__device__ float g_at[MTOT * DINNER];      // rounded act
__device__ float g_gt[MTOT * DINNER];      // rounded gated
__device__ float g_wt[DINNER * DINNER];    // rounded transposed weights (reused)

// ---------------------------------------------------------------------------
// PTX helpers
// ---------------------------------------------------------------------------
__device__ __forceinline__ uint32_t smem_u32(const void* p) {
    uint32_t a;
    asm("{ .reg .u64 t; cvta.to.shared.u64 t, %1; cvt.u32.u64 %0, t; }"
        : "=r"(a) : "l"(p));
    return a;
}
__device__ __forceinline__ void cpa16(uint32_t dst, const void* src) {
    asm volatile("cp.async.cg.shared.global [%0], [%1], 16;"
                 :: "r"(dst), "l"(src));
}
__device__ __forceinline__ uint32_t lds32(uint32_t addr) {
    uint32_t v;
    asm volatile("ld.shared.b32 %0, [%1];" : "=r"(v) : "r"(addr));
    return v;
}
__device__ __forceinline__ float to_tf32(float f) {
    uint32_t o, i = __float_as_uint(f);
    asm("cvt.rna.tf32.f32 %0, %1;" : "=r"(o) : "r"(i));
    return __uint_as_float(o);
}
__device__ __forceinline__ void mma_tf32(float* d, const uint32_t* a,
                                         uint32_t b0, uint32_t b1) {
    asm volatile(
        "mma.sync.aligned.m16n8k8.row.col.f32.tf32.tf32.f32 "
        "{%0,%1,%2,%3}, {%4,%5,%6,%7}, {%8,%9}, {%0,%1,%2,%3};"
        : "+f"(d[0]), "+f"(d[1]), "+f"(d[2]), "+f"(d[3])
        : "r"(a[0]), "r"(a[1]), "r"(a[2]), "r"(a[3]), "r"(b0), "r"(b1));
}

// ---------------------------------------------------------------------------
// tf32 mma.sync GEMM (identical to R13 — proven 233us on the fused shape)
// ---------------------------------------------------------------------------
#define MG_STAGE  16384        // A(8K) + B(8K)

__device__ __forceinline__ void load_stage(uint32_t sstage,
        const float* __restrict__ A, const float* __restrict__ B,
        int arow0, int brow0, int K, int kc, int tid)
{
#pragma unroll
    for (int it = 0; it < 2; it++) {
        const int idx = tid + 256 * it;      // 0..511
        const int rr  = idx >> 2;            // row 0..127
        const int c4  = idx & 3;             // 16B chunk
        const uint32_t soff = rr * 64 + ((c4 ^ ((rr >> 1) & 3)) << 4);
        cpa16(sstage +        soff, A + (size_t)(arow0 + rr) * K + kc + c4 * 4);
        cpa16(sstage + 8192 + soff, B + (size_t)(brow0 + rr) * K + kc + c4 * 4);
    }
}

template<int EPI>   // 0: bias, 1: bias + softplus
__global__ __launch_bounds__(256, 2)
void mmagemm(const float* __restrict__ A, const float* __restrict__ B,
             const float* __restrict__ bias0, const float* __restrict__ bias1,
             float* __restrict__ C0, float* __restrict__ C1,
             int Nout, int Nsplit, int K)
{
    __shared__ char smem[3 * MG_STAGE];     // 48 KB static
    const uint32_t sb = smem_u32(smem);
    const int tid  = threadIdx.x;
    const int wid  = tid >> 5;
    const int lane = tid & 31;
    const int warp_m = wid & 1;
    const int warp_n = wid >> 1;
    const int arow0 = blockIdx.y * 128;
    const int brow0 = blockIdx.x * 128;

    const int rA = lane >> 2;                 // 0..7
    const int cA = lane & 3;                  // 0..3
    const int swz = ((rA >> 1) & 3) << 2;
    uint32_t kx[2], kx4[2];
#pragma unroll
    for (int s = 0; s < 2; s++) {
        kx[s]  = (uint32_t)(((s * 8 + cA)     ^ swz) << 2);
        kx4[s] = (uint32_t)(((s * 8 + cA + 4) ^ swz) << 2);
    }
    const int m0 = warp_m * 64;
    const int n0 = warp_n * 32;

    float acc[4][4][4];
#pragma unroll
    for (int a = 0; a < 4; a++)
#pragma unroll
        for (int b = 0; b < 4; b++)
#pragma unroll
            for (int c = 0; c < 4; c++) acc[a][b][c] = 0.f;

    const int nch = K >> 4;

    load_stage(sb,            A, B, arow0, brow0, K, 0,  tid);
    asm volatile("cp.async.commit_group;");
    load_stage(sb + MG_STAGE, A, B, arow0, brow0, K, 16, tid);
    asm volatile("cp.async.commit_group;");

    int stage = 0;
    for (int i = 0; i < nch; i++) {
        if (i + 1 < nch) {
            asm volatile("cp.async.wait_group 1;");
        } else {
            asm volatile("cp.async.wait_group 0;");
        }
        __syncthreads();

        if (i + 2 < nch) {
            int ns = stage + 2; if (ns >= 3) ns -= 3;
            load_stage(sb + ns * MG_STAGE, A, B, arow0, brow0, K, (i + 2) * 16, tid);
            asm volatile("cp.async.commit_group;");
        }

        const uint32_t st = sb + stage * MG_STAGE;
#pragma unroll
        for (int ks = 0; ks < 2; ks++) {
            uint32_t bf[4][2];
#pragma unroll
            for (int nt = 0; nt < 4; nt++) {
                const uint32_t rb = st + 8192 + (n0 + nt * 8 + rA) * 64;
                bf[nt][0] = lds32(rb + kx[ks]);
                bf[nt][1] = lds32(rb + kx4[ks]);
            }
#pragma unroll
            for (int mt = 0; mt < 4; mt++) {
                const uint32_t ra = st + (m0 + mt * 16 + rA) * 64;
                uint32_t af[4];
                af[0] = lds32(ra +       kx[ks]);
                af[1] = lds32(ra + 512 + kx[ks]);
                af[2] = lds32(ra +       kx4[ks]);
                af[3] = lds32(ra + 512 + kx4[ks]);
#pragma unroll
                for (int nt = 0; nt < 4; nt++)
                    mma_tf32(acc[mt][nt], af, bf[nt][0], bf[nt][1]);
            }
        }
        if (++stage == 3) stage = 0;
    }

    const float* bias = bias0;
    float* Cp = C0;
    int colbase = brow0;
    if (brow0 >= Nsplit) { bias = bias1; Cp = C1; colbase = brow0 - Nsplit; }

    const int gid = lane >> 2, tig = lane & 3;
#pragma unroll
    for (int mt = 0; mt < 4; mt++) {
        const int r0 = arow0 + m0 + mt * 16 + gid;
#pragma unroll
        for (int nt = 0; nt < 4; nt++) {
            const int col = colbase + n0 + nt * 8 + tig * 2;
            const float bb0 = __ldg(bias + col);
            const float bb1 = __ldg(bias + col + 1);
            float v0 = acc[mt][nt][0] + bb0;
            float v1 = acc[mt][nt][1] + bb1;
            float v2 = acc[mt][nt][2] + bb0;
            float v3 = acc[mt][nt][3] + bb1;
            if (EPI == 1) {
                v0 = (v0 > 20.f) ? v0 : log1pf(expf(v0));
                v1 = (v1 > 20.f) ? v1 : log1pf(expf(v1));
                v2 = (v2 > 20.f) ? v2 : log1pf(expf(v2));
                v3 = (v3 > 20.f) ? v3 : log1pf(expf(v3));
            }
            float2 p01; p01.x = v0; p01.y = v1;
            float2 p23; p23.x = v2; p23.y = v3;
            *(float2*)(Cp + (size_t)r0 * Nout + col)       = p01;
            *(float2*)(Cp + (size_t)(r0 + 8) * Nout + col) = p23;
        }
    }
}

// ---------------------------------------------------------------------------
// Elementwise tf32 rounding (for input x)
// ---------------------------------------------------------------------------
__global__ __launch_bounds__(256)
void round_tf32(const float* __restrict__ in, float* __restrict__ out, int n4)
{
    const int i = blockIdx.x * 256 + threadIdx.x;
    if (i >= n4) return;
    float4 v = ((const float4*)in)[i];
    v.x = to_tf32(v.x); v.y = to_tf32(v.y);
    v.z = to_tf32(v.z); v.w = to_tf32(v.w);
    ((float4*)out)[i] = v;
}

// ---------------------------------------------------------------------------
// Weight transpose + tf32 round: W[K,N] -> T[N,K]
// ---------------------------------------------------------------------------
__global__ void transpose_tf32(const float* __restrict__ W, int K, int N,
                               float* __restrict__ T)
{
    __shared__ float ts[32][33];
    const int n0 = blockIdx.x * 32, k0 = blockIdx.y * 32;
    const int tx = threadIdx.x, ty = threadIdx.y;
#pragma unroll
    for (int i = 0; i < 4; i++)
        ts[ty + i * 8][tx] = W[(size_t)(k0 + ty + i * 8) * N + n0 + tx];
    __syncthreads();
#pragma unroll
    for (int i = 0; i < 4; i++)
        T[(size_t)(n0 + ty + i * 8) * K + k0 + tx] = to_tf32(ts[tx][ty + i * 8]);
}

// ---------------------------------------------------------------------------
// Causal depthwise conv (K=4) + bias + silu; outputs exact act + rounded copy
// ---------------------------------------------------------------------------
__global__ __launch_bounds__(256)
void conv_silu(const float* __restrict__ xz, const float* __restrict__ w,
               const float* __restrict__ cb, float* __restrict__ act,
               float* __restrict__ act_t)
{
    const int idx = blockIdx.x * 256 + threadIdx.x;
    if (idx >= MTOT * DINNER) return;
    const int d = idx & (DINNER - 1);
    const int bt = idx >> 11;
    const int t = bt & (LSEQ - 1);

    float s = __ldg(cb + d);
#pragma unroll
    for (int k = 0; k < KCONV; k++) {
        const int tt = t - (KCONV - 1) + k;
        if (tt >= 0)
            s = fmaf(__ldg(w + d * KCONV + k), xz[idx + (k - (KCONV - 1)) * DINNER], s);
    }
    const float v = s / (1.f + __expf(-s));
    act[idx]   = v;
    act_t[idx] = to_tf32(v);
}

// ---------------------------------------------------------------------------
// Skinny GEMM: Bm = act @ W_B, Cm = act @ W_C   (fp32, precision-critical)
// ---------------------------------------------------------------------------
__global__ __launch_bounds__(256)
void bc_gemm(const float* __restrict__ act,
             const float* __restrict__ WB, const float* __restrict__ WC,
             float* __restrict__ Bm, float* __restrict__ Cm)
{
    const int m = blockIdx.x * 16 + (threadIdx.x >> 4);
    const int n = threadIdx.x & 15;
    const float* a = act + (size_t)m * DINNER;

    float sb = 0.f, sc = 0.f;
#pragma unroll 8
    for (int k = 0; k < DINNER; k++) {
        const float av = a[k];
        sb = fmaf(av, __ldg(WB + k * NSTATE + n), sb);
        sc = fmaf(av, __ldg(WC + k * NSTATE + n), sc);
    }
    Bm[m * NSTATE + n] = sb;
    Cm[m * NSTATE + n] = sc;
}

// ---------------------------------------------------------------------------
// Selective scan + skip + gating.
// R13 structure: per-warp independent, MLP=8 batched direct loads, NO
// barriers. R14's one good idea kept: recurrence first, then the 8 butterfly
// reduction trees interleaved by level (in-order issue no longer serializes
// 32 dependent SHFLs). Same adds, same order -> bitwise-identical output.
// ---------------------------------------------------------------------------
__global__ __launch_bounds__(256)
void scan_kernel(const float* __restrict__ delta, const float* __restrict__ act,
                 const float* __restrict__ Bm, const float* __restrict__ Cm,
                 const float* __restrict__ A_log, const float* __restrict__ D_skip,
                 const float* __restrict__ xg, float* __restrict__ gt)
{
    const int w = blockIdx.x * 8 + (threadIdx.x >> 5);   // 0 .. 2047
    const int lane = threadIdx.x & 31;
    const int n = lane & 15;
    const int b = w >> 10;
    const int dp = w & 1023;
    const int d = dp * 2 + (lane >> 4);

    const float a = -expf(A_log[d * NSTATE + n]);
    const float dsk = D_skip[d];

    const float* pD = delta + (size_t)b * LSEQ * DINNER + d;
    const float* pX = act   + (size_t)b * LSEQ * DINNER + d;
    const float* pG = xg    + (size_t)b * LSEQ * DINNER + d;
    float*       pT = gt    + (size_t)b * LSEQ * DINNER + d;
    const float* pB = Bm + (size_t)b * LSEQ * NSTATE + n;
    const float* pC = Cm + (size_t)b * LSEQ * NSTATE + n;

    float h = 0.f;
    for (int t0 = 0; t0 < LSEQ; t0 += 8) {
        float dv[8], xv[8], gv[8], bv[8], cv[8];
#pragma unroll
        for (int jj = 0; jj < 8; jj++) {
            const size_t o = (size_t)(t0 + jj) * DINNER;
            dv[jj] = pD[o];
            xv[jj] = pX[o];
            gv[jj] = pG[o];
            bv[jj] = pB[(t0 + jj) * NSTATE];
            cv[jj] = pC[(t0 + jj) * NSTATE];
        }
        // Batched exps (independent of the h chain)
        float dA[8];
#pragma unroll
        for (int jj = 0; jj < 8; jj++) dA[jj] = __expf(dv[jj] * a);
        // Serial recurrence — the only true critical path (8 FMAs)
        float p[8];
#pragma unroll
        for (int jj = 0; jj < 8; jj++) {
            h = fmaf(dA[jj], h, (dv[jj] * xv[jj]) * bv[jj]);
            p[jj] = h * cv[jj];
        }
        // 8 butterfly trees, interleaved by level — pipelined SHFL latency
#pragma unroll
        for (int s = 1; s <= 8; s <<= 1) {
#pragma unroll
            for (int jj = 0; jj < 8; jj++)
                p[jj] += __shfl_xor_sync(0xffffffffu, p[jj], s);
        }
        if (n == 0) {
#pragma unroll
            for (int jj = 0; jj < 8; jj++) {
                const float g = gv[jj];
                const float y = (p[jj] + xv[jj] * dsk) * (g / (1.f + __expf(-g)));
                pT[(size_t)(t0 + jj) * DINNER] = to_tf32(y);
            }
        }
    }
}

// ---------------------------------------------------------------------------
// Launch
// ---------------------------------------------------------------------------
extern "C" void kernel_launch(void* const* d_in, const int* in_sizes, int n_in,
                              void* d_out, int out_size)
{
    const float* x      = (const float*)d_in[0];
    const float* W_in   = (const float*)d_in[1];
    const float* b_in   = (const float*)d_in[2];
    const float* W_gate = (const float*)d_in[3];
    const float* b_gate = (const float*)d_in[4];
    const float* conv_w = (const float*)d_in[5];
    const float* conv_b = (const float*)d_in[6];
    const float* A_log  = (const float*)d_in[7];
    const float* D_skip = (const float*)d_in[8];
    const float* W_delta= (const float*)d_in[9];
    const float* b_delta= (const float*)d_in[10];
    const float* W_B    = (const float*)d_in[11];
    const float* W_C    = (const float*)d_in[12];
    const float* W_out  = (const float*)d_in[13];
    const float* b_out  = (const float*)d_in[14];
    float* out = (float*)d_out;

    float *xz, *xg, *act, *delt, *Bm, *Cm, *xt, *at, *gt, *wt;
    cudaGetSymbolAddress((void**)&xz,   g_xz);
    cudaGetSymbolAddress((void**)&xg,   g_xg);
    cudaGetSymbolAddress((void**)&act,  g_act);
    cudaGetSymbolAddress((void**)&delt, g_delta);
    cudaGetSymbolAddress((void**)&Bm,   g_Bm);
    cudaGetSymbolAddress((void**)&Cm,   g_Cm);
    cudaGetSymbolAddress((void**)&xt,   g_xt);
    cudaGetSymbolAddress((void**)&at,   g_at);
    cudaGetSymbolAddress((void**)&gt,   g_gt);
    cudaGetSymbolAddress((void**)&wt,   g_wt);

    // 0) round x -> tf32
    {
        const int n4 = MTOT * DMODEL / 4;
        round_tf32<<<(n4 + 255) / 256, 256>>>(x, xt, n4);
    }
    // 1) fused in+gate: [xz | xg] = x @ [W_in | W_gate] + [b_in | b_gate]
    {
        dim3 tg(DINNER / 32, DMODEL / 32);
        transpose_tf32<<<tg, dim3(32, 8)>>>(W_in,   DMODEL, DINNER, wt);
        transpose_tf32<<<tg, dim3(32, 8)>>>(W_gate, DMODEL, DINNER,
                                            wt + (size_t)DINNER * DMODEL);
        dim3 grid(2 * DINNER / 128, MTOT / 128);     // 32 x 32
        mmagemm<0><<<grid, 256>>>(xt, wt, b_in, b_gate,
                                  xz, xg, DINNER, DINNER, DMODEL);
    }
    // 2) act = silu(conv(xz) + conv_b)  (+ tf32 copy)
    {
        const int total = MTOT * DINNER;
        conv_silu<<<(total + 255) / 256, 256>>>(xz, conv_w, conv_b, act, at);
    }
    // 3) delta = softplus(act @ W_delta + b_delta)
    {
        dim3 tg(DINNER / 32, DINNER / 32);
        transpose_tf32<<<tg, dim3(32, 8)>>>(W_delta, DINNER, DINNER, wt);
        dim3 grid(DINNER / 128, MTOT / 128);
        mmagemm<1><<<grid, 256>>>(at, wt, b_delta, b_delta,
                                  delt, delt, DINNER, DINNER, DINNER);
    }
    // 4) Bm, Cm
    {
        bc_gemm<<<MTOT / 16, 256>>>(act, W_B, W_C, Bm, Cm);
    }
    // 5) scan + skip + gating -> gt (tf32-rounded)
    {
        scan_kernel<<<(BATCH * DINNER / 2) / 8, 256>>>(delt, act, Bm, Cm,
                                                       A_log, D_skip, xg, gt);
    }
    // 6) out = gated @ W_out + b_out
    {
        dim3 tg(DMODEL / 32, DINNER / 32);
        transpose_tf32<<<tg, dim3(32, 8)>>>(W_out, DINNER, DMODEL, wt);
        dim3 grid(DMODEL / 128, MTOT / 128);
        mmagemm<0><<<grid, 256>>>(gt, wt, b_out, b_out,
                                  out, out, DMODEL, DMODEL, DINNER);
    }
}